// round 16
// baseline (speedup 1.0000x reference)
#include <cuda_runtime.h>
#include <cuda_fp16.h>
#include <cstdint>

#define Bq    64
#define Tq    512
#define NINPq 300
#define KXP   320
#define NK16X 20
#define Hh    512
#define H4    2048
#define D2    1024
#define NK16H 64
#define DAq   350
#define LDT1  352
#define Rq    30
#define MLPq  2000
#define KMq   30720
#define NCLS  5
#define MROWS (Bq*Tq)
#define MFR   (MROWS/16)
#define BH    (Bq*Hh)
#define NCTA  128
#define SKq   16

// ---- static scratch ----
__device__ uint4 g_xpf[(size_t)MFR*NK16X*32];
__device__ uint4 g_xpb[(size_t)MFR*NK16X*32];
__device__ uint4 g_Wpf[(size_t)128*NK16X*32];
__device__ uint4 g_Wpb[(size_t)128*NK16X*32];
__device__ uint4 g_W1p[(size_t)24*NK16H*32];
__device__ uint4 g_HoutP[(size_t)MFR*NK16H*32];
__device__ __half g_xg_f[(size_t)MROWS*H4];
__device__ __half g_xg_b[(size_t)MROWS*H4];
__device__ float g_Hout[(size_t)MROWS*D2];
__device__ float g_tanh1[(size_t)MROWS*LDT1];
__device__ float g_s2[(size_t)MROWS*Rq];
__device__ float g_A[(size_t)Bq*Rq*Tq];
__device__ float g_M[(size_t)Bq*Rq*D2];
__device__ __half g_hbuf[2*2*BH];
__device__ float g_part[(size_t)SKq*Bq*2048];
__device__ float g_hidden[Bq*MLPq];
__device__ float g_penal[Bq];
__device__ int   g_bar[4608];

__device__ __forceinline__ float tf32r(float x) {
    uint32_t u; asm("cvt.rna.tf32.f32 %0, %1;" : "=r"(u) : "f"(x));
    return __uint_as_float(u);
}
__device__ __forceinline__ uint32_t pack2(float a, float b) {
    __half2 h = __floats2half2_rn(a, b);
    return *reinterpret_cast<uint32_t*>(&h);
}
__device__ __forceinline__ float fsig(float x) {
    return __fdividef(1.f, 1.f + __expf(-x));
}
__device__ __forceinline__ float ftanh(float x) {
    float t = __expf(-2.f * fabsf(x));
    float r = __fdividef(1.f - t, 1.f + t);
    return copysignf(r, x);
}
__device__ __forceinline__ void mma8(float* d, const float* a, const float* b) {
    asm volatile("mma.sync.aligned.m16n8k8.row.col.f32.tf32.tf32.f32 "
        "{%0,%1,%2,%3},{%4,%5,%6,%7},{%8,%9},{%0,%1,%2,%3};\n"
        : "+f"(d[0]), "+f"(d[1]), "+f"(d[2]), "+f"(d[3])
        : "r"(__float_as_uint(a[0])), "r"(__float_as_uint(a[1])),
          "r"(__float_as_uint(a[2])), "r"(__float_as_uint(a[3])),
          "r"(__float_as_uint(b[0])), "r"(__float_as_uint(b[1])));
}
__device__ __forceinline__ void mma16(float* d, uint4 a, uint32_t b0, uint32_t b1) {
    asm volatile("mma.sync.aligned.m16n8k16.row.col.f32.f16.f16.f32 "
        "{%0,%1,%2,%3},{%4,%5,%6,%7},{%8,%9},{%0,%1,%2,%3};\n"
        : "+f"(d[0]), "+f"(d[1]), "+f"(d[2]), "+f"(d[3])
        : "r"(a.x), "r"(a.y), "r"(a.z), "r"(a.w), "r"(b0), "r"(b1));
}
__device__ __forceinline__ size_t pk16(int m, int k, int nk16) {
    return ((size_t)((m >> 4) * nk16 + (k >> 4)) * 32 + ((m & 7) << 2) + ((k & 7) >> 1)) * 8
           + (((k >> 3) & 1) << 2) + (((m >> 3) & 1) << 1) + (k & 1);
}

// ---- embed + mask -> packed fp16 xpf / xpb ; also zeroes hbuf + barriers ----
__global__ void sa_embed_kernel(const int* __restrict__ ids, const int* __restrict__ len,
                                const float* __restrict__ emb,
                                __half* __restrict__ xpf, __half* __restrict__ xpb,
                                __half* __restrict__ hb, int* __restrict__ bar)
{
    int bt = blockIdx.x, b = bt >> 9, t = bt & 511;
    if (bt < 128) {
        int zidx = bt * 128 + threadIdx.x;
        uint32_t* hbu = reinterpret_cast<uint32_t*>(hb);
        for (int i = zidx; i < 2 * 2 * BH / 2; i += 16384) hbu[i] = 0u;
        if (zidx < 4608) bar[zidx] = 0;
    }
    int L = len[b];
    int rt = (t < L) ? (L - 1 - t) : t;
    float mk = (t < L) ? 1.f : 0.f;
    const float* ef = emb + (size_t)ids[bt] * NINPq;
    const float* eb = emb + (size_t)ids[(b << 9) + rt] * NINPq;
    for (int k = threadIdx.x; k < KXP; k += blockDim.x) {
        size_t off = pk16(bt, k, NK16X);
        xpf[off] = __float2half_rn((k < NINPq) ? ef[k] * mk : 0.f);
        xpb[off] = __float2half_rn((k < NINPq) ? eb[k] * mk : 0.f);
    }
}

// ---- permute weight W[N][K] -> packed fp16 b-frag uint4s ----
__global__ void sa_permW16(const float* __restrict__ W, uint4* __restrict__ Wp,
                           int N, int K, int ldw, int nbp, int nk16)
{
    int idx = blockIdx.x * 256 + threadIdx.x;
    if (idx >= nbp * nk16 * 32) return;
    int lane = idx & 31, k16 = (idx >> 5) % nk16, nb = (idx >> 5) / nk16;
    int g = lane >> 2, tg = lane & 3;
    int c0 = nb * 16 + g, c1 = c0 + 8;
    int kb = k16 * 16 + 2 * tg;
    float v00 = 0.f, v01 = 0.f, v02 = 0.f, v03 = 0.f;
    float v10 = 0.f, v11 = 0.f, v12 = 0.f, v13 = 0.f;
    if (c0 < N) {
        if (kb     < K) v00 = W[(size_t)c0 * ldw + kb];
        if (kb + 1 < K) v01 = W[(size_t)c0 * ldw + kb + 1];
        if (kb + 8 < K) v02 = W[(size_t)c0 * ldw + kb + 8];
        if (kb + 9 < K) v03 = W[(size_t)c0 * ldw + kb + 9];
    }
    if (c1 < N) {
        if (kb     < K) v10 = W[(size_t)c1 * ldw + kb];
        if (kb + 1 < K) v11 = W[(size_t)c1 * ldw + kb + 1];
        if (kb + 8 < K) v12 = W[(size_t)c1 * ldw + kb + 8];
        if (kb + 9 < K) v13 = W[(size_t)c1 * ldw + kb + 9];
    }
    uint4 v;
    v.x = pack2(v00, v01); v.y = pack2(v02, v03);
    v.z = pack2(v10, v11); v.w = pack2(v12, v13);
    Wp[idx] = v;
}

// ---- packed fp16 GEMM v2 (CTA 64m x 128n, A+B through smem, double-buffered) ----
// act: 0 = none (float out), 1 = tanh (float out), 2 = none (half out)
// grid: x = ceil(N/128) (must match Wp nbp allocation), y = M/64
__global__ void __launch_bounds__(256)
sa_gemm_pk(const uint4* __restrict__ Ap, const uint4* __restrict__ Wp,
           float* __restrict__ C, int M, int N, int nk16, int ldc, int act)
{
    __shared__ uint4 As[2][512];     // [4 mfl][4 k16][32 lane]
    __shared__ uint4 Bs[2][1024];    // [8 nbl][4 k16][32 lane]
    int by = blockIdx.y, bn = blockIdx.x * 128;
    int tid = threadIdx.x, wid = tid >> 5, lane = tid & 31;
    int wm = wid & 1, wn = wid >> 1;
    int g = lane >> 2, tg = lane & 3;

    float acc[2][4][4];
#pragma unroll
    for (int mi = 0; mi < 2; mi++)
#pragma unroll
        for (int nb = 0; nb < 4; nb++)
#pragma unroll
            for (int e = 0; e < 4; e++) acc[mi][nb][e] = 0.f;

    // loader indices
    int aIdx = tid;                   // 2 per thread (stride 256) over 512
    int aMfl0 = aIdx >> 7, aK0 = (aIdx >> 5) & 3, aLn = aIdx & 31;
    int aMfl1 = (aIdx + 256) >> 7, aK1 = ((aIdx + 256) >> 5) & 3;
    int bNbl0 = tid >> 7, bK0 = (tid >> 5) & 3;   // 4 per thread over 1024

    int chunks = nk16 >> 2;
    // preload chunk 0
    As[0][tid]       = __ldg(Ap + ((size_t)(by * 4 + aMfl0) * nk16 + aK0) * 32 + aLn);
    As[0][tid + 256] = __ldg(Ap + ((size_t)(by * 4 + aMfl1) * nk16 + aK1) * 32 + aLn);
#pragma unroll
    for (int i = 0; i < 4; i++) {
        int idx = tid + i * 256;
        int nbl = idx >> 7, k16l = (idx >> 5) & 3, ln = idx & 31;
        Bs[0][idx] = __ldg(Wp + ((size_t)((bn >> 4) + nbl) * nk16 + k16l) * 32 + ln);
    }
    __syncthreads();

    for (int ch = 0; ch < chunks; ch++) {
        int buf = ch & 1;
        uint4 an0, an1, bnx[4];
        bool more = (ch + 1) < chunks;
        if (more) {
            int k16c = (ch + 1) << 2;
            an0 = __ldg(Ap + ((size_t)(by * 4 + aMfl0) * nk16 + k16c + aK0) * 32 + aLn);
            an1 = __ldg(Ap + ((size_t)(by * 4 + aMfl1) * nk16 + k16c + aK1) * 32 + aLn);
#pragma unroll
            for (int i = 0; i < 4; i++) {
                int idx = tid + i * 256;
                int nbl = idx >> 7, k16l = (idx >> 5) & 3, ln = idx & 31;
                bnx[i] = __ldg(Wp + ((size_t)((bn >> 4) + nbl) * nk16 + k16c + k16l) * 32 + ln);
            }
        }
#pragma unroll
        for (int k16l = 0; k16l < 4; k16l++) {
            uint4 a0 = As[buf][((wm * 2)     * 4 + k16l) * 32 + lane];
            uint4 a1 = As[buf][((wm * 2 + 1) * 4 + k16l) * 32 + lane];
            uint4 b0 = Bs[buf][((wn * 2)     * 4 + k16l) * 32 + lane];
            uint4 b1 = Bs[buf][((wn * 2 + 1) * 4 + k16l) * 32 + lane];
            mma16(acc[0][0], a0, b0.x, b0.y);
            mma16(acc[0][1], a0, b0.z, b0.w);
            mma16(acc[0][2], a0, b1.x, b1.y);
            mma16(acc[0][3], a0, b1.z, b1.w);
            mma16(acc[1][0], a1, b0.x, b0.y);
            mma16(acc[1][1], a1, b0.z, b0.w);
            mma16(acc[1][2], a1, b1.x, b1.y);
            mma16(acc[1][3], a1, b1.z, b1.w);
        }
        if (more) {
            As[buf ^ 1][tid]       = an0;
            As[buf ^ 1][tid + 256] = an1;
#pragma unroll
            for (int i = 0; i < 4; i++) Bs[buf ^ 1][tid + i * 256] = bnx[i];
        }
        __syncthreads();
    }
    if (act == 2) {
        __half* Ch = (__half*)C;
#pragma unroll
        for (int mi = 0; mi < 2; mi++)
#pragma unroll
            for (int nb = 0; nb < 4; nb++) {
                int row = by * 64 + (wm * 2 + mi) * 16 + g;
                int col = bn + wn * 32 + nb * 8 + 2 * tg;
                if (row < M && col < N) {
                    *(__half2*)(Ch + (size_t)row * ldc + col) =
                        __floats2half2_rn(acc[mi][nb][0], acc[mi][nb][1]);
                    if (row + 8 < M)
                        *(__half2*)(Ch + (size_t)(row + 8) * ldc + col) =
                            __floats2half2_rn(acc[mi][nb][2], acc[mi][nb][3]);
                }
            }
    } else {
#pragma unroll
        for (int mi = 0; mi < 2; mi++)
#pragma unroll
            for (int nb = 0; nb < 4; nb++)
#pragma unroll
                for (int e = 0; e < 4; e++) {
                    int row = by * 64 + (wm * 2 + mi) * 16 + g + ((e >> 1) << 3);
                    int col = bn + wn * 32 + nb * 8 + 2 * tg + (e & 1);
                    if (row < M && col < N) {
                        float v = acc[mi][nb][e];
                        if (act == 1) v = ftanh(v);
                        C[(size_t)row * ldc + col] = v;
                    }
                }
    }
}

// ---- legacy tf32 GEMM (row-major A) for W2 + MLP; skips MMA for fully-OOB m-warps ----
__global__ void __launch_bounds__(256)
sa_gemm_tf32(const float* __restrict__ A, const float* __restrict__ W,
             float* __restrict__ C, int M, int N, int K,
             int lda, int ldw, int ldc, int kchunk, int act)
{
    __shared__ float As[128][36];
    __shared__ float Bs[64][36];
    int kbeg = blockIdx.z * kchunk, kend = min(K, kbeg + kchunk);
    C += (size_t)blockIdx.z * (size_t)M * ldc;
    int bm = blockIdx.y * 128, bn = blockIdx.x * 64;
    int tid = threadIdx.x, wid = tid >> 5, lane = tid & 31;
    int wm = wid & 3, wn = wid >> 2;
    int g = lane >> 2, tg = lane & 3;
    bool mwork = (bm + wm * 32) < M;
    float acc[2][4][4];
#pragma unroll
    for (int mi = 0; mi < 2; mi++)
#pragma unroll
        for (int ni = 0; ni < 4; ni++)
#pragma unroll
            for (int e = 0; e < 4; e++) acc[mi][ni][e] = 0.f;
    int arow = tid >> 1;
    bool av = (bm + arow) < M;
    const float* Apt = A + (size_t)(bm + arow) * lda;
    int brow = tid >> 2;
    bool bv = (bn + brow) < N;
    const float* Bpt = W + (size_t)(bn + brow) * ldw;
    bool vec4 = ((K & 3) == 0) && ((lda & 3) == 0) && ((ldw & 3) == 0);
    for (int k0 = kbeg; k0 < kend; k0 += 32) {
        if (vec4) {
#pragma unroll
            for (int s = 0; s < 4; s++) {
                int kc = ((tid & 1) + s * 2) * 4, kk = k0 + kc;
                float4 v = make_float4(0.f, 0.f, 0.f, 0.f);
                if (av && kk < kend) v = *reinterpret_cast<const float4*>(Apt + kk);
                As[arow][kc] = tf32r(v.x); As[arow][kc + 1] = tf32r(v.y);
                As[arow][kc + 2] = tf32r(v.z); As[arow][kc + 3] = tf32r(v.w);
            }
#pragma unroll
            for (int s = 0; s < 2; s++) {
                int kc = ((tid & 3) + s * 4) * 4, kk = k0 + kc;
                float4 v = make_float4(0.f, 0.f, 0.f, 0.f);
                if (bv && kk < kend) v = *reinterpret_cast<const float4*>(Bpt + kk);
                Bs[brow][kc] = tf32r(v.x); Bs[brow][kc + 1] = tf32r(v.y);
                Bs[brow][kc + 2] = tf32r(v.z); Bs[brow][kc + 3] = tf32r(v.w);
            }
        } else {
#pragma unroll
            for (int i = 0; i < 16; i++) {
                int kc = (tid & 1) * 16 + i, kk = k0 + kc;
                As[arow][kc] = (av && kk < kend) ? tf32r(__ldg(Apt + kk)) : 0.f;
            }
#pragma unroll
            for (int i = 0; i < 8; i++) {
                int kc = (tid & 3) * 8 + i, kk = k0 + kc;
                Bs[brow][kc] = (bv && kk < kend) ? tf32r(__ldg(Bpt + kk)) : 0.f;
            }
        }
        __syncthreads();
        if (mwork) {
#pragma unroll
            for (int k8 = 0; k8 < 32; k8 += 8) {
                float a0[4], a1[4];
                int r0 = wm * 32;
                a0[0] = As[r0 + g][k8 + tg];          a0[1] = As[r0 + g + 8][k8 + tg];
                a0[2] = As[r0 + g][k8 + tg + 4];      a0[3] = As[r0 + g + 8][k8 + tg + 4];
                a1[0] = As[r0 + 16 + g][k8 + tg];     a1[1] = As[r0 + 24 + g][k8 + tg];
                a1[2] = As[r0 + 16 + g][k8 + tg + 4]; a1[3] = As[r0 + 24 + g][k8 + tg + 4];
#pragma unroll
                for (int ni = 0; ni < 4; ni++) {
                    float bf[2];
                    int cb = wn * 32 + ni * 8 + g;
                    bf[0] = Bs[cb][k8 + tg]; bf[1] = Bs[cb][k8 + tg + 4];
                    mma8(acc[0][ni], a0, bf);
                    mma8(acc[1][ni], a1, bf);
                }
            }
        }
        __syncthreads();
    }
#pragma unroll
    for (int mi = 0; mi < 2; mi++)
#pragma unroll
        for (int ni = 0; ni < 4; ni++)
#pragma unroll
            for (int e = 0; e < 4; e++) {
                int row = bm + wm * 32 + mi * 16 + g + (e >> 1) * 8;
                int col = bn + wn * 32 + ni * 8 + 2 * tg + (e & 1);
                if (row < M && col < N) {
                    float v = acc[mi][ni][e];
                    if (act == 1) v = ftanh(v);
                    C[(size_t)row * ldc + col] = v;
                }
            }
}

// ---- LSTM v10: split gate buffers, per-warp poll, xg prefetch, coalesced hnext ----
__global__ void __launch_bounds__(256, 1)
sa_lstm_kernel(const __half* __restrict__ xg_f, const __half* __restrict__ xg_b,
               const float* __restrict__ Whh_f, const float* __restrict__ Whh_b,
               const int* __restrict__ len, float* __restrict__ Hout,
               __half* __restrict__ HoutP, __half* __restrict__ hbuf, int* __restrict__ bar)
{
    extern __shared__ uint4 smU[];
    uint4* Wp4h = smU;                          // [4 gate][32 k16][32 lane] = 4096 (64KB)
    float* gate_sA = (float*)(smU + 4096);      // [64 col][33]
    float* gate_sB = gate_sA + 64 * 33;         // [64 col][33]
    __half* hst = (__half*)(gate_sB + 64 * 33); // [2 frel][256] staged hnext

    const int tid = threadIdx.x, wid = tid >> 5, lane = tid & 31;
    const int wm = wid & 1, wk = (wid >> 1) & 1, wn = wid >> 2;
    const int g = lane >> 2, tg = lane & 3;
    const int dir = blockIdx.x >> 6, cta = blockIdx.x & 63;
    const int bh = cta >> 5, gb = cta & 31, jj0 = gb << 4;
    const __half* xg = dir ? xg_b : xg_f;
    const float* Whh = dir ? Whh_b : Whh_f;
    __half* hb = hbuf + dir * 2 * BH;
    int* barBase = bar + (dir * 2 + bh) * 512;
    float* gate_w = wk ? gate_sB : gate_sA;

    for (int idx = tid; idx < 4096; idx += 256) {
        int nbp = idx >> 10, rem = idx & 1023, k16 = rem >> 5, ln = rem & 31;
        int gB = ln >> 2, tgi = ln & 3;
        int r0 = (nbp << 9) + jj0 + gB;
        int r1 = r0 + 8;
        int kb = k16 * 16 + 2 * tgi;
        uint4 v;
        v.x = pack2(Whh[(size_t)r0 * 512 + kb],     Whh[(size_t)r0 * 512 + kb + 1]);
        v.y = pack2(Whh[(size_t)r0 * 512 + kb + 8], Whh[(size_t)r0 * 512 + kb + 9]);
        v.z = pack2(Whh[(size_t)r1 * 512 + kb],     Whh[(size_t)r1 * 512 + kb + 1]);
        v.w = pack2(Whh[(size_t)r1 * 512 + kb + 8], Whh[(size_t)r1 * 512 + kb + 9]);
        Wp4h[idx] = v;
    }
    const int jl = tid & 15, bl = tid >> 4;
    const int bg0 = (bh << 5) + bl, bg1 = bg0 + 16;
    const int L0 = len[bg0], L1 = len[bg1];
    float cst0 = 0.f, cst1 = 0.f;
    const int f = bh * 2 + wm;
    const __half* xp0base = xg + (size_t)(bg0 << 9) * H4 + jj0 + jl;
    const __half* xp1base = xg + (size_t)(bg1 << 9) * H4 + jj0 + jl;
    const int hoff = (((bl & 7) << 2) + ((jl & 7) >> 1)) * 8
                   + (((jl >> 3) & 1) << 2) + (((bl >> 3) & 1) << 1) + (jl & 1);

    float xv0[4], xv1[4];
#pragma unroll
    for (int G = 0; G < 4; G++) {
        xv0[G] = __half2float(__ldg(xp0base + (G << 9)));
        xv1[G] = __half2float(__ldg(xp1base + (G << 9)));
    }
    __syncthreads();

    for (int t = 0; t < Tq; t++) {
        const uint4* hin4 = reinterpret_cast<const uint4*>(hb + (t & 1) * BH);
        uint4* hn4 = reinterpret_cast<uint4*>(hb + ((t & 1) ^ 1) * BH);

        float acc[4][4];
#pragma unroll
        for (int nb = 0; nb < 4; nb++)
#pragma unroll
            for (int e = 0; e < 4; e++) acc[nb][e] = 0.f;

        uint4 af[4], afn[4];
        const int k16base = wk << 4;
#pragma unroll
        for (int j = 0; j < 4; j++)
            af[j] = __ldcg(hin4 + (size_t)(f * 32 + k16base + j) * 32 + lane);
#pragma unroll
        for (int rnd = 0; rnd < 4; rnd++) {
            int kb = k16base + rnd * 4;
            if (rnd < 3) {
#pragma unroll
                for (int j = 0; j < 4; j++)
                    afn[j] = __ldcg(hin4 + (size_t)(f * 32 + kb + 4 + j) * 32 + lane);
            }
#pragma unroll
            for (int j = 0; j < 4; j++) {
                int k16 = kb + j;
                uint4 b0 = Wp4h[((wn * 2) << 10) + k16 * 32 + lane];
                uint4 b1 = Wp4h[((wn * 2 + 1) << 10) + k16 * 32 + lane];
                mma16(acc[0], af[j], b0.x, b0.y);
                mma16(acc[1], af[j], b0.z, b0.w);
                mma16(acc[2], af[j], b1.x, b1.y);
                mma16(acc[3], af[j], b1.z, b1.w);
            }
            if (rnd < 3) {
#pragma unroll
                for (int j = 0; j < 4; j++) af[j] = afn[j];
            }
        }
#pragma unroll
        for (int nb = 0; nb < 4; nb++)
#pragma unroll
            for (int e = 0; e < 4; e++) {
                int b = wm * 16 + g + ((e >> 1) << 3);
                int c = wn * 32 + nb * 8 + 2 * tg + (e & 1);
                gate_w[c * 33 + b] = acc[nb][e];
            }
        __syncthreads();

        float hv0s, hv1s;
#pragma unroll
        for (int pp = 0; pp < 2; pp++) {
            int bloc = pp ? bl + 16 : bl;
            const float* xv = pp ? xv1 : xv0;
            float pi = gate_sA[(jl)      * 33 + bloc] + gate_sB[(jl)      * 33 + bloc] + xv[0];
            float pf = gate_sA[(16 + jl) * 33 + bloc] + gate_sB[(16 + jl) * 33 + bloc] + xv[1];
            float pg = gate_sA[(32 + jl) * 33 + bloc] + gate_sB[(32 + jl) * 33 + bloc] + xv[2];
            float po = gate_sA[(48 + jl) * 33 + bloc] + gate_sB[(48 + jl) * 33 + bloc] + xv[3];
            float si = fsig(pi);
            float sf = fsig(pf);
            float so = fsig(po);
            float tg2 = ftanh(pg);
            float cv = pp ? cst1 : cst0;
            cv = sf * cv + si * tg2;
            if (pp) cst1 = cv; else cst0 = cv;
            float hv = so * ftanh(cv);
            hst[(pp << 8) + hoff] = __float2half_rn(hv);
            if (pp) hv1s = hv; else hv0s = hv;
        }
        __syncthreads();

        if (wid == 0) {
            const uint4* hs4 = reinterpret_cast<const uint4*>(hst);
            hn4[((size_t)((bh * 2)     * 32 + gb)) * 32 + lane] = hs4[lane];
            hn4[((size_t)((bh * 2 + 1) * 32 + gb)) * 32 + lane] = hs4[32 + lane];
            __syncwarp();
            if (lane == 0 && t < Tq - 1) {
                asm volatile("red.release.gpu.global.add.s32 [%0], 1;" :: "l"(barBase + t) : "memory");
            }
        }
#pragma unroll
        for (int pp = 0; pp < 2; pp++) {
            int b = pp ? bg1 : bg0;
            int L = pp ? L1 : L0;
            float hv = pp ? hv1s : hv0s;
            int tpos = t;
            if (dir) tpos = (t < L) ? (L - 1 - t) : t;
            int m = (b << 9) + tpos, kch = (dir << 9) + jj0 + jl;
            Hout[(size_t)m * D2 + kch] = hv;
            HoutP[pk16(m, kch, NK16H)] = __float2half_rn(hv);
        }
        if (t < Tq - 1) {
#pragma unroll
            for (int G = 0; G < 4; G++) {
                xv0[G] = __half2float(__ldg(xp0base + (size_t)(t + 1) * H4 + (G << 9)));
                xv1[G] = __half2float(__ldg(xp1base + (size_t)(t + 1) * H4 + (G << 9)));
            }
            if (lane == 0) {
                int v;
                do {
                    asm volatile("ld.acquire.gpu.global.s32 %0, [%1];" : "=r"(v) : "l"(barBase + t) : "memory");
                } while (v < 32);
            }
            __syncwarp();
        }
    }
}

// ---- masked softmax ----
__global__ void sa_softmax_kernel(const float* __restrict__ s2, const int* __restrict__ len,
                                  float* __restrict__ A)
{
    __shared__ float red[256];
    int b = blockIdx.x / Rq, r = blockIdx.x % Rq;
    int L = len[b];
    const float* src = s2 + (size_t)(b * Tq) * Rq + r;
    float* dst = A + (size_t)(b * Rq + r) * Tq;
    int tid = threadIdx.x;
    float m = -1e30f;
    for (int t = tid; t < L; t += 256) m = fmaxf(m, src[(size_t)t * Rq]);
    red[tid] = m; __syncthreads();
    for (int s = 128; s > 0; s >>= 1) { if (tid < s) red[tid] = fmaxf(red[tid], red[tid + s]); __syncthreads(); }
    m = red[0]; __syncthreads();
    float sum = 0.f;
    for (int t = tid; t < Tq; t += 256) {
        float e = (t < L) ? __expf(src[(size_t)t * Rq] - m) : 0.f;
        dst[t] = e; sum += e;
    }
    red[tid] = sum; __syncthreads();
    for (int s = 128; s > 0; s >>= 1) { if (tid < s) red[tid] += red[tid + s]; __syncthreads(); }
    float inv = __fdividef(1.f, red[0]);
    for (int t = tid; t < Tq; t += 256) dst[t] *= inv;
}

// ---- M = A @ Hout ----
__global__ void sa_attnM_kernel(const float* __restrict__ A, const float* __restrict__ Hout,
                                float* __restrict__ Mout)
{
    extern __shared__ float As[];
    int b = blockIdx.x, h0 = blockIdx.y * 128, tid = threadIdx.x;
    const float* Ab = A + (size_t)b * Rq * Tq;
    for (int i = tid; i < Rq * Tq; i += 128) As[i] = Ab[i];
    __syncthreads();
    int h = h0 + tid;
    float acc[Rq];
#pragma unroll
    for (int r = 0; r < Rq; r++) acc[r] = 0.f;
    const float* Hb = Hout + (size_t)(b * Tq) * D2 + h;
    for (int t = 0; t < Tq; t += 4) {
        float hv0 = __ldg(Hb + (size_t)t * D2);
        float hv1 = __ldg(Hb + (size_t)(t + 1) * D2);
        float hv2 = __ldg(Hb + (size_t)(t + 2) * D2);
        float hv3 = __ldg(Hb + (size_t)(t + 3) * D2);
#pragma unroll
        for (int r = 0; r < Rq; r++) {
            float4 a4 = *(const float4*)&As[r * Tq + t];
            acc[r] += a4.x * hv0 + a4.y * hv1 + a4.z * hv2 + a4.w * hv3;
        }
    }
#pragma unroll
    for (int r = 0; r < Rq; r++) Mout[(size_t)(b * Rq + r) * D2 + h] = acc[r];
}

// ---- penal ----
__global__ void sa_penal_kernel(const float* __restrict__ A, float* __restrict__ out)
{
    extern __shared__ float As[];
    __shared__ float red[256];
    int b = blockIdx.x, tid = threadIdx.x;
    const float* Ab = A + (size_t)b * Rq * Tq;
    for (int i = tid; i < Rq * Tq; i += 256) As[i] = Ab[i];
    __syncthreads();
    float local = 0.f;
    for (int p = tid; p < Rq * Rq; p += 256) {
        int r = p / Rq, s = p % Rq;
        float d = 0.f;
        for (int t = 0; t < Tq; t += 4) {
            float4 x = *(const float4*)&As[r * Tq + t];
            float4 y = *(const float4*)&As[s * Tq + t];
            d += x.x * y.x + x.y * y.y + x.z * y.z + x.w * y.w;
        }
        if (r == s) d -= 1.f;
        local += d * d;
    }
    red[tid] = local; __syncthreads();
    for (int s = 128; s > 0; s >>= 1) { if (tid < s) red[tid] += red[tid + s]; __syncthreads(); }
    if (tid == 0) out[b] = red[0];
}

__global__ void sa_reduce_hidden_kernel(const float* __restrict__ part, const float* __restrict__ bm,
                                        float* __restrict__ hidden)
{
    int idx = blockIdx.x * 256 + threadIdx.x;
    if (idx >= Bq * MLPq) return;
    int row = idx / MLPq, col = idx % MLPq;
    float s = 0.f;
#pragma unroll
    for (int z = 0; z < SKq; z++) s += part[(size_t)z * Bq * 2048 + row * 2048 + col];
    s += bm[col];
    hidden[idx] = fmaxf(s, 0.f);
}

__global__ void sa_decode_kernel(const float* __restrict__ hidden, const float* __restrict__ Wd,
                                 const float* __restrict__ bd, float* __restrict__ out)
{
    int b = blockIdx.x;
    int w = threadIdx.x >> 5, l = threadIdx.x & 31;
    const float* hbp = hidden + b * MLPq;
    const float* wr = Wd + w * MLPq;
    float s = 0.f;
    for (int k = l; k < MLPq; k += 32) s += hbp[k] * wr[k];
    for (int o = 16; o > 0; o >>= 1) s += __shfl_down_sync(0xffffffffu, s, o);
    if (l == 0) out[b * NCLS + w] = s + bd[w];
}

__global__ void sa_penal_final_kernel(const float* __restrict__ pen, float* __restrict__ out)
{
    __shared__ float red[64];
    int tid = threadIdx.x;
    red[tid] = pen[tid]; __syncthreads();
    for (int s = 32; s > 0; s >>= 1) { if (tid < s) red[tid] += red[tid + s]; __syncthreads(); }
    if (tid == 0) out[Bq * NCLS] = red[0] / 64.f;
}

extern "C" void kernel_launch(void* const* d_in, const int* in_sizes, int n_in,
                              void* d_out, int out_size)
{
    (void)in_sizes; (void)n_in; (void)out_size;
    const int*   ids  = (const int*)d_in[0];
    const int*   len  = (const int*)d_in[1];
    const float* emb  = (const float*)d_in[2];
    const float* Wihf = (const float*)d_in[3];
    const float* Whhf = (const float*)d_in[4];
    const float* Wihb = (const float*)d_in[5];
    const float* Whhb = (const float*)d_in[6];
    const float* W1   = (const float*)d_in[7];
    const float* W2   = (const float*)d_in[8];
    const float* Wm   = (const float*)d_in[9];
    const float* bm   = (const float*)d_in[10];
    const float* Wd   = (const float*)d_in[11];
    const float* bd   = (const float*)d_in[12];
    float* out = (float*)d_out;

    uint4 *pxpf, *pxpb, *pWpf, *pWpb, *pW1p, *pHP;
    __half *pxgf, *pxgb, *phb;
    float *pH, *pt1, *ps2, *pA, *pM, *ppart, *phid, *ppen;
    int* pbar;
    cudaGetSymbolAddress((void**)&pxpf,  g_xpf);
    cudaGetSymbolAddress((void**)&pxpb,  g_xpb);
    cudaGetSymbolAddress((void**)&pWpf,  g_Wpf);
    cudaGetSymbolAddress((void**)&pWpb,  g_Wpb);
    cudaGetSymbolAddress((void**)&pW1p,  g_W1p);
    cudaGetSymbolAddress((void**)&pHP,   g_HoutP);
    cudaGetSymbolAddress((void**)&pxgf,  g_xg_f);
    cudaGetSymbolAddress((void**)&pxgb,  g_xg_b);
    cudaGetSymbolAddress((void**)&pH,    g_Hout);
    cudaGetSymbolAddress((void**)&pt1,   g_tanh1);
    cudaGetSymbolAddress((void**)&ps2,   g_s2);
    cudaGetSymbolAddress((void**)&pA,    g_A);
    cudaGetSymbolAddress((void**)&pM,    g_M);
    cudaGetSymbolAddress((void**)&phb,   g_hbuf);
    cudaGetSymbolAddress((void**)&ppart, g_part);
    cudaGetSymbolAddress((void**)&phid,  g_hidden);
    cudaGetSymbolAddress((void**)&ppen,  g_penal);
    cudaGetSymbolAddress((void**)&pbar,  g_bar);

    const int lstm_smem = 122880;
    cudaFuncSetAttribute(sa_lstm_kernel,  cudaFuncAttributeMaxDynamicSharedMemorySize, lstm_smem);
    cudaFuncSetAttribute(sa_attnM_kernel, cudaFuncAttributeMaxDynamicSharedMemorySize, Rq * Tq * 4);
    cudaFuncSetAttribute(sa_penal_kernel, cudaFuncAttributeMaxDynamicSharedMemorySize, Rq * Tq * 4);

    sa_embed_kernel<<<Bq * Tq, 128>>>(ids, len, emb, (__half*)pxpf, (__half*)pxpb, phb, pbar);
    sa_permW16<<<(128 * NK16X * 32 + 255) / 256, 256>>>(Wihf, pWpf, H4, NINPq, NINPq, 128, NK16X);
    sa_permW16<<<(128 * NK16X * 32 + 255) / 256, 256>>>(Wihb, pWpb, H4, NINPq, NINPq, 128, NK16X);

    sa_gemm_pk<<<dim3(16, 512), 256>>>(pxpf, pWpf, (float*)pxgf, MROWS, H4, NK16X, H4, 2);
    sa_gemm_pk<<<dim3(16, 512), 256>>>(pxpb, pWpb, (float*)pxgb, MROWS, H4, NK16X, H4, 2);

    sa_lstm_kernel<<<NCTA, 256, lstm_smem>>>(pxgf, pxgb, Whhf, Whhb, len, pH, (__half*)pHP, phb, pbar);

    sa_permW16<<<(24 * NK16H * 32 + 255) / 256, 256>>>(W1, pW1p, DAq, D2, D2, 24, NK16H);
    sa_gemm_pk<<<dim3(3, 512), 256>>>(pHP, pW1p, pt1, MROWS, DAq, NK16H, LDT1, 1);
    sa_gemm_tf32<<<dim3(1, MROWS / 128, 1), 256>>>(pt1, W2, ps2, MROWS, Rq, DAq, LDT1, DAq, Rq, DAq, 0);
    sa_softmax_kernel<<<Bq * Rq, 256>>>(ps2, len, pA);
    sa_attnM_kernel<<<dim3(Bq, D2 / 128), 128, Rq * Tq * 4>>>(pA, pH, pM);
    sa_penal_kernel<<<Bq, 256, Rq * Tq * 4>>>(pA, ppen);
    sa_gemm_tf32<<<dim3((MLPq + 63) / 64, 1, SKq), 256>>>(pM, Wm, ppart, Bq, MLPq, KMq, KMq, KMq, 2048, KMq / SKq, 0);
    sa_reduce_hidden_kernel<<<(Bq * MLPq + 255) / 256, 256>>>(ppart, bm, phid);
    sa_decode_kernel<<<Bq, 160>>>(phid, Wd, bd, out);
    sa_penal_final_kernel<<<1, 64>>>(ppen, out);
}

// round 17
// speedup vs baseline: 1.0826x; 1.0826x over previous
#include <cuda_runtime.h>
#include <cuda_fp16.h>
#include <cstdint>

#define Bq    64
#define Tq    512
#define NINPq 300
#define KXP   320
#define NK16X 20
#define Hh    512
#define H4    2048
#define D2    1024
#define NK16H 64
#define DAq   350
#define LDT1  352
#define Rq    30
#define MLPq  2000
#define KMq   30720
#define NCLS  5
#define MROWS (Bq*Tq)
#define MFR   (MROWS/16)
#define BH    (Bq*Hh)
#define NCTA  128
#define SKq   16

// ---- static scratch ----
__device__ uint4 g_xpf[(size_t)MFR*NK16X*32];
__device__ uint4 g_xpb[(size_t)MFR*NK16X*32];
__device__ uint4 g_Wpf[(size_t)128*NK16X*32];
__device__ uint4 g_Wpb[(size_t)128*NK16X*32];
__device__ uint4 g_W1p[(size_t)24*NK16H*32];
__device__ uint4 g_HoutP[(size_t)MFR*NK16H*32];
__device__ __half g_xg_f[(size_t)MROWS*H4];
__device__ __half g_xg_b[(size_t)MROWS*H4];
__device__ float g_Hout[(size_t)MROWS*D2];
__device__ float g_tanh1[(size_t)MROWS*LDT1];
__device__ float g_s2[(size_t)MROWS*Rq];
__device__ float g_A[(size_t)Bq*Rq*Tq];
__device__ float g_M[(size_t)Bq*Rq*D2];
__device__ __half g_hbuf[2*2*BH];
__device__ float g_part[(size_t)SKq*Bq*2048];
__device__ float g_hidden[Bq*MLPq];
__device__ float g_penal[Bq];
__device__ int   g_bar[4608];

__device__ __forceinline__ float tf32r(float x) {
    uint32_t u; asm("cvt.rna.tf32.f32 %0, %1;" : "=r"(u) : "f"(x));
    return __uint_as_float(u);
}
__device__ __forceinline__ uint32_t pack2(float a, float b) {
    __half2 h = __floats2half2_rn(a, b);
    return *reinterpret_cast<uint32_t*>(&h);
}
__device__ __forceinline__ float fsig(float x) {
    return __fdividef(1.f, 1.f + __expf(-x));
}
__device__ __forceinline__ float ftanh(float x) {
    float t = __expf(-2.f * fabsf(x));
    float r = __fdividef(1.f - t, 1.f + t);
    return copysignf(r, x);
}
__device__ __forceinline__ void mma8(float* d, const float* a, const float* b) {
    asm volatile("mma.sync.aligned.m16n8k8.row.col.f32.tf32.tf32.f32 "
        "{%0,%1,%2,%3},{%4,%5,%6,%7},{%8,%9},{%0,%1,%2,%3};\n"
        : "+f"(d[0]), "+f"(d[1]), "+f"(d[2]), "+f"(d[3])
        : "r"(__float_as_uint(a[0])), "r"(__float_as_uint(a[1])),
          "r"(__float_as_uint(a[2])), "r"(__float_as_uint(a[3])),
          "r"(__float_as_uint(b[0])), "r"(__float_as_uint(b[1])));
}
__device__ __forceinline__ void mma16(float* d, uint4 a, uint32_t b0, uint32_t b1) {
    asm volatile("mma.sync.aligned.m16n8k16.row.col.f32.f16.f16.f32 "
        "{%0,%1,%2,%3},{%4,%5,%6,%7},{%8,%9},{%0,%1,%2,%3};\n"
        : "+f"(d[0]), "+f"(d[1]), "+f"(d[2]), "+f"(d[3])
        : "r"(a.x), "r"(a.y), "r"(a.z), "r"(a.w), "r"(b0), "r"(b1));
}
__device__ __forceinline__ size_t pk16(int m, int k, int nk16) {
    return ((size_t)((m >> 4) * nk16 + (k >> 4)) * 32 + ((m & 7) << 2) + ((k & 7) >> 1)) * 8
           + (((k >> 3) & 1) << 2) + (((m >> 3) & 1) << 1) + (k & 1);
}

// ---- embed + mask -> packed fp16 xpf / xpb ; also zeroes hbuf + barriers ----
__global__ void sa_embed_kernel(const int* __restrict__ ids, const int* __restrict__ len,
                                const float* __restrict__ emb,
                                __half* __restrict__ xpf, __half* __restrict__ xpb,
                                __half* __restrict__ hb, int* __restrict__ bar)
{
    int bt = blockIdx.x, b = bt >> 9, t = bt & 511;
    if (bt < 128) {
        int zidx = bt * 128 + threadIdx.x;
        uint32_t* hbu = reinterpret_cast<uint32_t*>(hb);
        for (int i = zidx; i < 2 * 2 * BH / 2; i += 16384) hbu[i] = 0u;
        if (zidx < 4608) bar[zidx] = 0;
    }
    int L = len[b];
    int rt = (t < L) ? (L - 1 - t) : t;
    float mk = (t < L) ? 1.f : 0.f;
    const float* ef = emb + (size_t)ids[bt] * NINPq;
    const float* eb = emb + (size_t)ids[(b << 9) + rt] * NINPq;
    for (int k = threadIdx.x; k < KXP; k += blockDim.x) {
        size_t off = pk16(bt, k, NK16X);
        xpf[off] = __float2half_rn((k < NINPq) ? ef[k] * mk : 0.f);
        xpb[off] = __float2half_rn((k < NINPq) ? eb[k] * mk : 0.f);
    }
}

// ---- permute weight W[N][K] -> packed fp16 b-frag uint4s ----
__global__ void sa_permW16(const float* __restrict__ W, uint4* __restrict__ Wp,
                           int N, int K, int ldw, int nbp, int nk16)
{
    int idx = blockIdx.x * 256 + threadIdx.x;
    if (idx >= nbp * nk16 * 32) return;
    int lane = idx & 31, k16 = (idx >> 5) % nk16, nb = (idx >> 5) / nk16;
    int g = lane >> 2, tg = lane & 3;
    int c0 = nb * 16 + g, c1 = c0 + 8;
    int kb = k16 * 16 + 2 * tg;
    float v00 = 0.f, v01 = 0.f, v02 = 0.f, v03 = 0.f;
    float v10 = 0.f, v11 = 0.f, v12 = 0.f, v13 = 0.f;
    if (c0 < N) {
        if (kb     < K) v00 = W[(size_t)c0 * ldw + kb];
        if (kb + 1 < K) v01 = W[(size_t)c0 * ldw + kb + 1];
        if (kb + 8 < K) v02 = W[(size_t)c0 * ldw + kb + 8];
        if (kb + 9 < K) v03 = W[(size_t)c0 * ldw + kb + 9];
    }
    if (c1 < N) {
        if (kb     < K) v10 = W[(size_t)c1 * ldw + kb];
        if (kb + 1 < K) v11 = W[(size_t)c1 * ldw + kb + 1];
        if (kb + 8 < K) v12 = W[(size_t)c1 * ldw + kb + 8];
        if (kb + 9 < K) v13 = W[(size_t)c1 * ldw + kb + 9];
    }
    uint4 v;
    v.x = pack2(v00, v01); v.y = pack2(v02, v03);
    v.z = pack2(v10, v11); v.w = pack2(v12, v13);
    Wp[idx] = v;
}

// ---- packed fp16 GEMM (R15 register-A version + padded-block skip) ----
// act: 0 = none (float out), 1 = tanh (float out), 2 = none (half out)
// lenArr: if non-null, M rows are (b<<9)+t; blocks with t0 >= len[b] are skipped
//         (act==2: write zero tile; act==1: return, output unread).
__global__ void __launch_bounds__(256)
sa_gemm_pk(const uint4* __restrict__ Ap, const uint4* __restrict__ Wp,
           float* __restrict__ C, int M, int N, int nk16, int ldc, int act,
           const int* __restrict__ lenArr)
{
    __shared__ uint4 Bsp[2][512];
    int bm16 = blockIdx.y * 8, bn = blockIdx.x * 64;
    int tid = threadIdx.x, wid = tid >> 5, lane = tid & 31;
    int wm = wid & 3, wn = wid >> 2;
    int g = lane >> 2, tg = lane & 3;

    if (lenArr) {
        int row0 = bm16 << 4;
        int b = row0 >> 9, t0 = row0 & 511;
        if (t0 >= lenArr[b]) {
            if (act == 2) {
                // write zero tile: 128 rows x 64 half cols = 1024 uint4
                uint4 z = make_uint4(0u, 0u, 0u, 0u);
                __half* Ch = (__half*)C;
#pragma unroll
                for (int i = 0; i < 4; i++) {
                    int idx = tid + i * 256;
                    int r = idx >> 3, q = idx & 7;
                    *reinterpret_cast<uint4*>(Ch + (size_t)(row0 + r) * ldc + bn + q * 8) = z;
                }
            }
            return;
        }
    }

    float acc[2][4][4];
#pragma unroll
    for (int mi = 0; mi < 2; mi++)
#pragma unroll
        for (int nb = 0; nb < 4; nb++)
#pragma unroll
            for (int e = 0; e < 4; e++) acc[mi][nb][e] = 0.f;

    int nbl0 = tid >> 7, k16l0 = (tid >> 5) & 3, ln0 = tid & 31;
    int nbl1 = (tid + 256) >> 7, k16l1 = ((tid + 256) >> 5) & 3;

    int chunks = nk16 >> 2;
    Bsp[0][tid]       = __ldg(Wp + ((size_t)((bn >> 4) + nbl0) * nk16 + k16l0) * 32 + ln0);
    Bsp[0][tid + 256] = __ldg(Wp + ((size_t)((bn >> 4) + nbl1) * nk16 + k16l1) * 32 + ln0);
    uint4 af[2][4];
#pragma unroll
    for (int mi = 0; mi < 2; mi++)
#pragma unroll
        for (int k16l = 0; k16l < 4; k16l++)
            af[mi][k16l] = __ldg(Ap + ((size_t)(bm16 + wm * 2 + mi) * nk16 + k16l) * 32 + lane);
    __syncthreads();

    for (int ch = 0; ch < chunks; ch++) {
        int buf = ch & 1;
        uint4 bn0, bn1, afn[2][4];
        bool more = (ch + 1) < chunks;
        if (more) {
            int k16c = (ch + 1) << 2;
            bn0 = __ldg(Wp + ((size_t)((bn >> 4) + nbl0) * nk16 + k16c + k16l0) * 32 + ln0);
            bn1 = __ldg(Wp + ((size_t)((bn >> 4) + nbl1) * nk16 + k16c + k16l1) * 32 + ln0);
#pragma unroll
            for (int mi = 0; mi < 2; mi++)
#pragma unroll
                for (int k16l = 0; k16l < 4; k16l++)
                    afn[mi][k16l] = __ldg(Ap + ((size_t)(bm16 + wm * 2 + mi) * nk16 + k16c + k16l) * 32 + lane);
        }
#pragma unroll
        for (int k16l = 0; k16l < 4; k16l++) {
            uint4 b0 = Bsp[buf][((wn * 2) * 4 + k16l) * 32 + lane];
            uint4 b1 = Bsp[buf][((wn * 2 + 1) * 4 + k16l) * 32 + lane];
#pragma unroll
            for (int mi = 0; mi < 2; mi++) {
                mma16(acc[mi][0], af[mi][k16l], b0.x, b0.y);
                mma16(acc[mi][1], af[mi][k16l], b0.z, b0.w);
                mma16(acc[mi][2], af[mi][k16l], b1.x, b1.y);
                mma16(acc[mi][3], af[mi][k16l], b1.z, b1.w);
            }
        }
        if (more) {
            Bsp[buf ^ 1][tid]       = bn0;
            Bsp[buf ^ 1][tid + 256] = bn1;
#pragma unroll
            for (int mi = 0; mi < 2; mi++)
#pragma unroll
                for (int k16l = 0; k16l < 4; k16l++) af[mi][k16l] = afn[mi][k16l];
        }
        __syncthreads();
    }
    if (act == 2) {
        __half* Ch = (__half*)C;
#pragma unroll
        for (int mi = 0; mi < 2; mi++)
#pragma unroll
            for (int nb = 0; nb < 4; nb++) {
                int row = bm16 * 16 + wm * 32 + mi * 16 + g;
                int col = bn + wn * 32 + nb * 8 + 2 * tg;
                if (row < M && col < N) {
                    *(__half2*)(Ch + (size_t)row * ldc + col) =
                        __floats2half2_rn(acc[mi][nb][0], acc[mi][nb][1]);
                    if (row + 8 < M)
                        *(__half2*)(Ch + (size_t)(row + 8) * ldc + col) =
                            __floats2half2_rn(acc[mi][nb][2], acc[mi][nb][3]);
                }
            }
    } else {
#pragma unroll
        for (int mi = 0; mi < 2; mi++)
#pragma unroll
            for (int nb = 0; nb < 4; nb++)
#pragma unroll
                for (int e = 0; e < 4; e++) {
                    int row = bm16 * 16 + wm * 32 + mi * 16 + g + ((e >> 1) << 3);
                    int col = bn + wn * 32 + nb * 8 + 2 * tg + (e & 1);
                    if (row < M && col < N) {
                        float v = acc[mi][nb][e];
                        if (act == 1) v = ftanh(v);
                        C[(size_t)row * ldc + col] = v;
                    }
                }
    }
}

// ---- legacy tf32 GEMM (row-major A) for W2 + MLP; m-warp skip + padded-block skip ----
__global__ void __launch_bounds__(256)
sa_gemm_tf32(const float* __restrict__ A, const float* __restrict__ W,
             float* __restrict__ C, int M, int N, int K,
             int lda, int ldw, int ldc, int kchunk, int act,
             const int* __restrict__ lenArr)
{
    __shared__ float As[128][36];
    __shared__ float Bs[64][36];
    int kbeg = blockIdx.z * kchunk, kend = min(K, kbeg + kchunk);
    C += (size_t)blockIdx.z * (size_t)M * ldc;
    int bm = blockIdx.y * 128, bn = blockIdx.x * 64;
    if (lenArr) {
        int b = bm >> 9, t0 = bm & 511;
        if (t0 >= lenArr[b]) return;   // output rows never read downstream
    }
    int tid = threadIdx.x, wid = tid >> 5, lane = tid & 31;
    int wm = wid & 3, wn = wid >> 2;
    int g = lane >> 2, tg = lane & 3;
    bool mwork = (bm + wm * 32) < M;
    float acc[2][4][4];
#pragma unroll
    for (int mi = 0; mi < 2; mi++)
#pragma unroll
        for (int ni = 0; ni < 4; ni++)
#pragma unroll
            for (int e = 0; e < 4; e++) acc[mi][ni][e] = 0.f;
    int arow = tid >> 1;
    bool av = (bm + arow) < M;
    const float* Apt = A + (size_t)(bm + arow) * lda;
    int brow = tid >> 2;
    bool bv = (bn + brow) < N;
    const float* Bpt = W + (size_t)(bn + brow) * ldw;
    bool vec4 = ((K & 3) == 0) && ((lda & 3) == 0) && ((ldw & 3) == 0);
    for (int k0 = kbeg; k0 < kend; k0 += 32) {
        if (vec4) {
#pragma unroll
            for (int s = 0; s < 4; s++) {
                int kc = ((tid & 1) + s * 2) * 4, kk = k0 + kc;
                float4 v = make_float4(0.f, 0.f, 0.f, 0.f);
                if (av && kk < kend) v = *reinterpret_cast<const float4*>(Apt + kk);
                As[arow][kc] = tf32r(v.x); As[arow][kc + 1] = tf32r(v.y);
                As[arow][kc + 2] = tf32r(v.z); As[arow][kc + 3] = tf32r(v.w);
            }
#pragma unroll
            for (int s = 0; s < 2; s++) {
                int kc = ((tid & 3) + s * 4) * 4, kk = k0 + kc;
                float4 v = make_float4(0.f, 0.f, 0.f, 0.f);
                if (bv && kk < kend) v = *reinterpret_cast<const float4*>(Bpt + kk);
                Bs[brow][kc] = tf32r(v.x); Bs[brow][kc + 1] = tf32r(v.y);
                Bs[brow][kc + 2] = tf32r(v.z); Bs[brow][kc + 3] = tf32r(v.w);
            }
        } else {
#pragma unroll
            for (int i = 0; i < 16; i++) {
                int kc = (tid & 1) * 16 + i, kk = k0 + kc;
                As[arow][kc] = (av && kk < kend) ? tf32r(__ldg(Apt + kk)) : 0.f;
            }
#pragma unroll
            for (int i = 0; i < 8; i++) {
                int kc = (tid & 3) * 8 + i, kk = k0 + kc;
                Bs[brow][kc] = (bv && kk < kend) ? tf32r(__ldg(Bpt + kk)) : 0.f;
            }
        }
        __syncthreads();
        if (mwork) {
#pragma unroll
            for (int k8 = 0; k8 < 32; k8 += 8) {
                float a0[4], a1[4];
                int r0 = wm * 32;
                a0[0] = As[r0 + g][k8 + tg];          a0[1] = As[r0 + g + 8][k8 + tg];
                a0[2] = As[r0 + g][k8 + tg + 4];      a0[3] = As[r0 + g + 8][k8 + tg + 4];
                a1[0] = As[r0 + 16 + g][k8 + tg];     a1[1] = As[r0 + 24 + g][k8 + tg];
                a1[2] = As[r0 + 16 + g][k8 + tg + 4]; a1[3] = As[r0 + 24 + g][k8 + tg + 4];
#pragma unroll
                for (int ni = 0; ni < 4; ni++) {
                    float bf[2];
                    int cb = wn * 32 + ni * 8 + g;
                    bf[0] = Bs[cb][k8 + tg]; bf[1] = Bs[cb][k8 + tg + 4];
                    mma8(acc[0][ni], a0, bf);
                    mma8(acc[1][ni], a1, bf);
                }
            }
        }
        __syncthreads();
    }
#pragma unroll
    for (int mi = 0; mi < 2; mi++)
#pragma unroll
        for (int ni = 0; ni < 4; ni++)
#pragma unroll
            for (int e = 0; e < 4; e++) {
                int row = bm + wm * 32 + mi * 16 + g + (e >> 1) * 8;
                int col = bn + wn * 32 + ni * 8 + 2 * tg + (e & 1);
                if (row < M && col < N) {
                    float v = acc[mi][ni][e];
                    if (act == 1) v = ftanh(v);
                    C[(size_t)row * ldc + col] = v;
                }
            }
}

// ---- LSTM v10: split gate buffers, per-warp poll, xg prefetch, coalesced hnext ----
__global__ void __launch_bounds__(256, 1)
sa_lstm_kernel(const __half* __restrict__ xg_f, const __half* __restrict__ xg_b,
               const float* __restrict__ Whh_f, const float* __restrict__ Whh_b,
               const int* __restrict__ len, float* __restrict__ Hout,
               __half* __restrict__ HoutP, __half* __restrict__ hbuf, int* __restrict__ bar)
{
    extern __shared__ uint4 smU[];
    uint4* Wp4h = smU;                          // [4 gate][32 k16][32 lane] = 4096 (64KB)
    float* gate_sA = (float*)(smU + 4096);      // [64 col][33]
    float* gate_sB = gate_sA + 64 * 33;         // [64 col][33]
    __half* hst = (__half*)(gate_sB + 64 * 33); // [2 frel][256] staged hnext

    const int tid = threadIdx.x, wid = tid >> 5, lane = tid & 31;
    const int wm = wid & 1, wk = (wid >> 1) & 1, wn = wid >> 2;
    const int g = lane >> 2, tg = lane & 3;
    const int dir = blockIdx.x >> 6, cta = blockIdx.x & 63;
    const int bh = cta >> 5, gb = cta & 31, jj0 = gb << 4;
    const __half* xg = dir ? xg_b : xg_f;
    const float* Whh = dir ? Whh_b : Whh_f;
    __half* hb = hbuf + dir * 2 * BH;
    int* barBase = bar + (dir * 2 + bh) * 512;
    float* gate_w = wk ? gate_sB : gate_sA;

    for (int idx = tid; idx < 4096; idx += 256) {
        int nbp = idx >> 10, rem = idx & 1023, k16 = rem >> 5, ln = rem & 31;
        int gB = ln >> 2, tgi = ln & 3;
        int r0 = (nbp << 9) + jj0 + gB;
        int r1 = r0 + 8;
        int kb = k16 * 16 + 2 * tgi;
        uint4 v;
        v.x = pack2(Whh[(size_t)r0 * 512 + kb],     Whh[(size_t)r0 * 512 + kb + 1]);
        v.y = pack2(Whh[(size_t)r0 * 512 + kb + 8], Whh[(size_t)r0 * 512 + kb + 9]);
        v.z = pack2(Whh[(size_t)r1 * 512 + kb],     Whh[(size_t)r1 * 512 + kb + 1]);
        v.w = pack2(Whh[(size_t)r1 * 512 + kb + 8], Whh[(size_t)r1 * 512 + kb + 9]);
        Wp4h[idx] = v;
    }
    const int jl = tid & 15, bl = tid >> 4;
    const int bg0 = (bh << 5) + bl, bg1 = bg0 + 16;
    const int L0 = len[bg0], L1 = len[bg1];
    float cst0 = 0.f, cst1 = 0.f;
    const int f = bh * 2 + wm;
    const __half* xp0base = xg + (size_t)(bg0 << 9) * H4 + jj0 + jl;
    const __half* xp1base = xg + (size_t)(bg1 << 9) * H4 + jj0 + jl;
    const int hoff = (((bl & 7) << 2) + ((jl & 7) >> 1)) * 8
                   + (((jl >> 3) & 1) << 2) + (((bl >> 3) & 1) << 1) + (jl & 1);

    float xv0[4], xv1[4];
#pragma unroll
    for (int G = 0; G < 4; G++) {
        xv0[G] = __half2float(__ldg(xp0base + (G << 9)));
        xv1[G] = __half2float(__ldg(xp1base + (G << 9)));
    }
    __syncthreads();

    for (int t = 0; t < Tq; t++) {
        const uint4* hin4 = reinterpret_cast<const uint4*>(hb + (t & 1) * BH);
        uint4* hn4 = reinterpret_cast<uint4*>(hb + ((t & 1) ^ 1) * BH);

        float acc[4][4];
#pragma unroll
        for (int nb = 0; nb < 4; nb++)
#pragma unroll
            for (int e = 0; e < 4; e++) acc[nb][e] = 0.f;

        uint4 af[4], afn[4];
        const int k16base = wk << 4;
#pragma unroll
        for (int j = 0; j < 4; j++)
            af[j] = __ldcg(hin4 + (size_t)(f * 32 + k16base + j) * 32 + lane);
#pragma unroll
        for (int rnd = 0; rnd < 4; rnd++) {
            int kb = k16base + rnd * 4;
            if (rnd < 3) {
#pragma unroll
                for (int j = 0; j < 4; j++)
                    afn[j] = __ldcg(hin4 + (size_t)(f * 32 + kb + 4 + j) * 32 + lane);
            }
#pragma unroll
            for (int j = 0; j < 4; j++) {
                int k16 = kb + j;
                uint4 b0 = Wp4h[((wn * 2) << 10) + k16 * 32 + lane];
                uint4 b1 = Wp4h[((wn * 2 + 1) << 10) + k16 * 32 + lane];
                mma16(acc[0], af[j], b0.x, b0.y);
                mma16(acc[1], af[j], b0.z, b0.w);
                mma16(acc[2], af[j], b1.x, b1.y);
                mma16(acc[3], af[j], b1.z, b1.w);
            }
            if (rnd < 3) {
#pragma unroll
                for (int j = 0; j < 4; j++) af[j] = afn[j];
            }
        }
#pragma unroll
        for (int nb = 0; nb < 4; nb++)
#pragma unroll
            for (int e = 0; e < 4; e++) {
                int b = wm * 16 + g + ((e >> 1) << 3);
                int c = wn * 32 + nb * 8 + 2 * tg + (e & 1);
                gate_w[c * 33 + b] = acc[nb][e];
            }
        __syncthreads();

        float hv0s, hv1s;
#pragma unroll
        for (int pp = 0; pp < 2; pp++) {
            int bloc = pp ? bl + 16 : bl;
            const float* xv = pp ? xv1 : xv0;
            float pi = gate_sA[(jl)      * 33 + bloc] + gate_sB[(jl)      * 33 + bloc] + xv[0];
            float pf = gate_sA[(16 + jl) * 33 + bloc] + gate_sB[(16 + jl) * 33 + bloc] + xv[1];
            float pg = gate_sA[(32 + jl) * 33 + bloc] + gate_sB[(32 + jl) * 33 + bloc] + xv[2];
            float po = gate_sA[(48 + jl) * 33 + bloc] + gate_sB[(48 + jl) * 33 + bloc] + xv[3];
            float si = fsig(pi);
            float sf = fsig(pf);
            float so = fsig(po);
            float tg2 = ftanh(pg);
            float cv = pp ? cst1 : cst0;
            cv = sf * cv + si * tg2;
            if (pp) cst1 = cv; else cst0 = cv;
            float hv = so * ftanh(cv);
            hst[(pp << 8) + hoff] = __float2half_rn(hv);
            if (pp) hv1s = hv; else hv0s = hv;
        }
        __syncthreads();

        if (wid == 0) {
            const uint4* hs4 = reinterpret_cast<const uint4*>(hst);
            hn4[((size_t)((bh * 2)     * 32 + gb)) * 32 + lane] = hs4[lane];
            hn4[((size_t)((bh * 2 + 1) * 32 + gb)) * 32 + lane] = hs4[32 + lane];
            __syncwarp();
            if (lane == 0 && t < Tq - 1) {
                asm volatile("red.release.gpu.global.add.s32 [%0], 1;" :: "l"(barBase + t) : "memory");
            }
        }
#pragma unroll
        for (int pp = 0; pp < 2; pp++) {
            int b = pp ? bg1 : bg0;
            int L = pp ? L1 : L0;
            float hv = pp ? hv1s : hv0s;
            int tpos = t;
            if (dir) tpos = (t < L) ? (L - 1 - t) : t;
            int m = (b << 9) + tpos, kch = (dir << 9) + jj0 + jl;
            Hout[(size_t)m * D2 + kch] = hv;
            HoutP[pk16(m, kch, NK16H)] = __float2half_rn(hv);
        }
        if (t < Tq - 1) {
#pragma unroll
            for (int G = 0; G < 4; G++) {
                xv0[G] = __half2float(__ldg(xp0base + (size_t)(t + 1) * H4 + (G << 9)));
                xv1[G] = __half2float(__ldg(xp1base + (size_t)(t + 1) * H4 + (G << 9)));
            }
            if (lane == 0) {
                int v;
                do {
                    asm volatile("ld.acquire.gpu.global.s32 %0, [%1];" : "=r"(v) : "l"(barBase + t) : "memory");
                } while (v < 32);
            }
            __syncwarp();
        }
    }
}

// ---- masked softmax ----
__global__ void sa_softmax_kernel(const float* __restrict__ s2, const int* __restrict__ len,
                                  float* __restrict__ A)
{
    __shared__ float red[256];
    int b = blockIdx.x / Rq, r = blockIdx.x % Rq;
    int L = len[b];
    const float* src = s2 + (size_t)(b * Tq) * Rq + r;
    float* dst = A + (size_t)(b * Rq + r) * Tq;
    int tid = threadIdx.x;
    float m = -1e30f;
    for (int t = tid; t < L; t += 256) m = fmaxf(m, src[(size_t)t * Rq]);
    red[tid] = m; __syncthreads();
    for (int s = 128; s > 0; s >>= 1) { if (tid < s) red[tid] = fmaxf(red[tid], red[tid + s]); __syncthreads(); }
    m = red[0]; __syncthreads();
    float sum = 0.f;
    for (int t = tid; t < Tq; t += 256) {
        float e = (t < L) ? __expf(src[(size_t)t * Rq] - m) : 0.f;
        dst[t] = e; sum += e;
    }
    red[tid] = sum; __syncthreads();
    for (int s = 128; s > 0; s >>= 1) { if (tid < s) red[tid] += red[tid + s]; __syncthreads(); }
    float inv = __fdividef(1.f, red[0]);
    for (int t = tid; t < Tq; t += 256) dst[t] *= inv;
}

// ---- M = A @ Hout ----
__global__ void sa_attnM_kernel(const float* __restrict__ A, const float* __restrict__ Hout,
                                float* __restrict__ Mout)
{
    extern __shared__ float As[];
    int b = blockIdx.x, h0 = blockIdx.y * 128, tid = threadIdx.x;
    const float* Ab = A + (size_t)b * Rq * Tq;
    for (int i = tid; i < Rq * Tq; i += 128) As[i] = Ab[i];
    __syncthreads();
    int h = h0 + tid;
    float acc[Rq];
#pragma unroll
    for (int r = 0; r < Rq; r++) acc[r] = 0.f;
    const float* Hb = Hout + (size_t)(b * Tq) * D2 + h;
    for (int t = 0; t < Tq; t += 4) {
        float hv0 = __ldg(Hb + (size_t)t * D2);
        float hv1 = __ldg(Hb + (size_t)(t + 1) * D2);
        float hv2 = __ldg(Hb + (size_t)(t + 2) * D2);
        float hv3 = __ldg(Hb + (size_t)(t + 3) * D2);
#pragma unroll
        for (int r = 0; r < Rq; r++) {
            float4 a4 = *(const float4*)&As[r * Tq + t];
            acc[r] += a4.x * hv0 + a4.y * hv1 + a4.z * hv2 + a4.w * hv3;
        }
    }
#pragma unroll
    for (int r = 0; r < Rq; r++) Mout[(size_t)(b * Rq + r) * D2 + h] = acc[r];
}

// ---- penal ----
__global__ void sa_penal_kernel(const float* __restrict__ A, float* __restrict__ out)
{
    extern __shared__ float As[];
    __shared__ float red[256];
    int b = blockIdx.x, tid = threadIdx.x;
    const float* Ab = A + (size_t)b * Rq * Tq;
    for (int i = tid; i < Rq * Tq; i += 256) As[i] = Ab[i];
    __syncthreads();
    float local = 0.f;
    for (int p = tid; p < Rq * Rq; p += 256) {
        int r = p / Rq, s = p % Rq;
        float d = 0.f;
        for (int t = 0; t < Tq; t += 4) {
            float4 x = *(const float4*)&As[r * Tq + t];
            float4 y = *(const float4*)&As[s * Tq + t];
            d += x.x * y.x + x.y * y.y + x.z * y.z + x.w * y.w;
        }
        if (r == s) d -= 1.f;
        local += d * d;
    }
    red[tid] = local; __syncthreads();
    for (int s = 128; s > 0; s >>= 1) { if (tid < s) red[tid] += red[tid + s]; __syncthreads(); }
    if (tid == 0) out[b] = red[0];
}

__global__ void sa_reduce_hidden_kernel(const float* __restrict__ part, const float* __restrict__ bm,
                                        float* __restrict__ hidden)
{
    int idx = blockIdx.x * 256 + threadIdx.x;
    if (idx >= Bq * MLPq) return;
    int row = idx / MLPq, col = idx % MLPq;
    float s = 0.f;
#pragma unroll
    for (int z = 0; z < SKq; z++) s += part[(size_t)z * Bq * 2048 + row * 2048 + col];
    s += bm[col];
    hidden[idx] = fmaxf(s, 0.f);
}

__global__ void sa_decode_kernel(const float* __restrict__ hidden, const float* __restrict__ Wd,
                                 const float* __restrict__ bd, float* __restrict__ out)
{
    int b = blockIdx.x;
    int w = threadIdx.x >> 5, l = threadIdx.x & 31;
    const float* hbp = hidden + b * MLPq;
    const float* wr = Wd + w * MLPq;
    float s = 0.f;
    for (int k = l; k < MLPq; k += 32) s += hbp[k] * wr[k];
    for (int o = 16; o > 0; o >>= 1) s += __shfl_down_sync(0xffffffffu, s, o);
    if (l == 0) out[b * NCLS + w] = s + bd[w];
}

__global__ void sa_penal_final_kernel(const float* __restrict__ pen, float* __restrict__ out)
{
    __shared__ float red[64];
    int tid = threadIdx.x;
    red[tid] = pen[tid]; __syncthreads();
    for (int s = 32; s > 0; s >>= 1) { if (tid < s) red[tid] += red[tid + s]; __syncthreads(); }
    if (tid == 0) out[Bq * NCLS] = red[0] / 64.f;
}

extern "C" void kernel_launch(void* const* d_in, const int* in_sizes, int n_in,
                              void* d_out, int out_size)
{
    (void)in_sizes; (void)n_in; (void)out_size;
    const int*   ids  = (const int*)d_in[0];
    const int*   len  = (const int*)d_in[1];
    const float* emb  = (const float*)d_in[2];
    const float* Wihf = (const float*)d_in[3];
    const float* Whhf = (const float*)d_in[4];
    const float* Wihb = (const float*)d_in[5];
    const float* Whhb = (const float*)d_in[6];
    const float* W1   = (const float*)d_in[7];
    const float* W2   = (const float*)d_in[8];
    const float* Wm   = (const float*)d_in[9];
    const float* bm   = (const float*)d_in[10];
    const float* Wd   = (const float*)d_in[11];
    const float* bd   = (const float*)d_in[12];
    float* out = (float*)d_out;

    uint4 *pxpf, *pxpb, *pWpf, *pWpb, *pW1p, *pHP;
    __half *pxgf, *pxgb, *phb;
    float *pH, *pt1, *ps2, *pA, *pM, *ppart, *phid, *ppen;
    int* pbar;
    cudaGetSymbolAddress((void**)&pxpf,  g_xpf);
    cudaGetSymbolAddress((void**)&pxpb,  g_xpb);
    cudaGetSymbolAddress((void**)&pWpf,  g_Wpf);
    cudaGetSymbolAddress((void**)&pWpb,  g_Wpb);
    cudaGetSymbolAddress((void**)&pW1p,  g_W1p);
    cudaGetSymbolAddress((void**)&pHP,   g_HoutP);
    cudaGetSymbolAddress((void**)&pxgf,  g_xg_f);
    cudaGetSymbolAddress((void**)&pxgb,  g_xg_b);
    cudaGetSymbolAddress((void**)&pH,    g_Hout);
    cudaGetSymbolAddress((void**)&pt1,   g_tanh1);
    cudaGetSymbolAddress((void**)&ps2,   g_s2);
    cudaGetSymbolAddress((void**)&pA,    g_A);
    cudaGetSymbolAddress((void**)&pM,    g_M);
    cudaGetSymbolAddress((void**)&phb,   g_hbuf);
    cudaGetSymbolAddress((void**)&ppart, g_part);
    cudaGetSymbolAddress((void**)&phid,  g_hidden);
    cudaGetSymbolAddress((void**)&ppen,  g_penal);
    cudaGetSymbolAddress((void**)&pbar,  g_bar);

    const int lstm_smem = 122880;
    cudaFuncSetAttribute(sa_lstm_kernel,  cudaFuncAttributeMaxDynamicSharedMemorySize, lstm_smem);
    cudaFuncSetAttribute(sa_attnM_kernel, cudaFuncAttributeMaxDynamicSharedMemorySize, Rq * Tq * 4);
    cudaFuncSetAttribute(sa_penal_kernel, cudaFuncAttributeMaxDynamicSharedMemorySize, Rq * Tq * 4);

    sa_embed_kernel<<<Bq * Tq, 128>>>(ids, len, emb, (__half*)pxpf, (__half*)pxpb, phb, pbar);
    sa_permW16<<<(128 * NK16X * 32 + 255) / 256, 256>>>(Wihf, pWpf, H4, NINPq, NINPq, 128, NK16X);
    sa_permW16<<<(128 * NK16X * 32 + 255) / 256, 256>>>(Wihb, pWpb, H4, NINPq, NINPq, 128, NK16X);

    sa_gemm_pk<<<dim3(32, 256), 256>>>(pxpf, pWpf, (float*)pxgf, MROWS, H4, NK16X, H4, 2, len);
    sa_gemm_pk<<<dim3(32, 256), 256>>>(pxpb, pWpb, (float*)pxgb, MROWS, H4, NK16X, H4, 2, len);

    sa_lstm_kernel<<<NCTA, 256, lstm_smem>>>(pxgf, pxgb, Whhf, Whhb, len, pH, (__half*)pHP, phb, pbar);

    sa_permW16<<<(24 * NK16H * 32 + 255) / 256, 256>>>(W1, pW1p, DAq, D2, D2, 24, NK16H);
    sa_gemm_pk<<<dim3(6, 256), 256>>>(pHP, pW1p, pt1, MROWS, DAq, NK16H, LDT1, 1, len);
    sa_gemm_tf32<<<dim3(1, MROWS / 128, 1), 256>>>(pt1, W2, ps2, MROWS, Rq, DAq, LDT1, DAq, Rq, DAq, 0, len);
    sa_softmax_kernel<<<Bq * Rq, 256>>>(ps2, len, pA);
    sa_attnM_kernel<<<dim3(Bq, D2 / 128), 128, Rq * Tq * 4>>>(pA, pH, pM);
    sa_penal_kernel<<<Bq, 256, Rq * Tq * 4>>>(pA, ppen);
    sa_gemm_tf32<<<dim3((MLPq + 63) / 64, 1, SKq), 256>>>(pM, Wm, ppart, Bq, MLPq, KMq, KMq, KMq, 2048, KMq / SKq, 0, nullptr);
    sa_reduce_hidden_kernel<<<(Bq * MLPq + 255) / 256, 256>>>(ppart, bm, phid);
    sa_decode_kernel<<<Bq, 160>>>(phid, Wd, bd, out);
    sa_penal_final_kernel<<<1, 64>>>(ppen, out);
}